// round 1
// baseline (speedup 1.0000x reference)
#include <cuda_runtime.h>
#include <cstdint>

#define HID 64
#define H2  128
#define NSEG 64
#define CH 2048
#define MAXN 50048
#define MAXT 1600512
#define MAXCHUNKS 800

// ---------------- device scratch (no allocations allowed) ----------------
__device__ float g_P[MAXN * H2];                 // 25.6 MB  h @ W1[:64,:]
__device__ unsigned long long g_pack[MAXT];      // sorted edges: src|dst<<16|conn<<32
__device__ unsigned g_ulog[MAXT];                // order-preserving uint32 logits
__device__ int g_hist[MAXCHUNKS * NSEG];         // per-chunk seg histograms -> offsets
__device__ int g_posCnt[NSEG];
__device__ int g_segStart[NSEG + 1];
__device__ int g_segCnt[NSEG];
__device__ int g_k[NSEG];
__device__ unsigned g_thr[NSEG];
__device__ int g_rem[NSEG];

// ---------------- zero scratch + node_mask region ----------------
__global__ void k_zero(float* outNM, int N) {
    int i = blockIdx.x * blockDim.x + threadIdx.x;
    if (i < N) outNM[i] = 0.0f;
    if (i < NSEG) g_posCnt[i] = 0;
}

// ---------------- P = h @ W1[:64,:]  (50000x64 @ 64x128) ----------------
__global__ __launch_bounds__(256) void k_gemmP(const float* __restrict__ h,
                                               const float* __restrict__ W1, int N) {
    __shared__ float Ws[HID][H2];
    int tid = threadIdx.x;
    for (int i = tid; i < HID * H2; i += 256) Ws[i / H2][i % H2] = W1[i];
    __syncthreads();
    int w = tid >> 5, lane = tid & 31;
    int j = lane * 4;
    int nw = gridDim.x * 8;
    for (int n = blockIdx.x * 8 + w; n < N; n += nw) {
        float h0 = h[n * HID + lane];
        float h1 = h[n * HID + 32 + lane];
        float4 acc = make_float4(0.f, 0.f, 0.f, 0.f);
#pragma unroll
        for (int k = 0; k < 64; k++) {
            float hv = __shfl_sync(0xffffffffu, (k < 32) ? h0 : h1, k & 31);
            float4 wv = *(const float4*)&Ws[k][j];
            acc.x += hv * wv.x; acc.y += hv * wv.y;
            acc.z += hv * wv.z; acc.w += hv * wv.w;
        }
        *(float4*)&g_P[n * H2 + j] = acc;
    }
}

// ---------------- per-chunk seg histograms (all + pos-only) ----------------
__global__ __launch_bounds__(256) void k_hist(const int* __restrict__ pos,
                                              const int* __restrict__ neg,
                                              const int* __restrict__ nb, int E, int T) {
    __shared__ int sh[NSEG];
    __shared__ int shp[NSEG];
    int tid = threadIdx.x;
    if (tid < NSEG) { sh[tid] = 0; shp[tid] = 0; }
    __syncthreads();
    int chunk = blockIdx.x;
    int base = chunk * CH;
    for (int i = tid; i < CH; i += 256) {
        int e = base + i;
        if (e < T) {
            int src = (e < E) ? pos[e] : neg[e - E];
            int s = nb[src];
            atomicAdd(&sh[s], 1);
            if (e < E) atomicAdd(&shp[s], 1);
        }
    }
    __syncthreads();
    if (tid < NSEG) {
        g_hist[chunk * NSEG + tid] = sh[tid];
        if (shp[tid]) atomicAdd(&g_posCnt[tid], shp[tid]);
    }
}

// ---------------- scan: seg starts, k, per-chunk offsets ----------------
__global__ void k_scan(int numChunks) {
    __shared__ int tot[NSEG];
    __shared__ int sstart[NSEG + 1];
    int s = threadIdx.x;  // 64 threads
    int t = 0;
    for (int c = 0; c < numChunks; c++) t += g_hist[c * NSEG + s];
    tot[s] = t;
    __syncthreads();
    if (s == 0) {
        int acc = 0;
        for (int i = 0; i < NSEG; i++) { sstart[i] = acc; acc += tot[i]; }
        sstart[NSEG] = acc;
    }
    __syncthreads();
    g_segStart[s] = sstart[s];
    if (s == 0) g_segStart[NSEG] = sstart[NSEG];
    g_segCnt[s] = tot[s];
    // replicate jax f32 rounding: floor(count_f32 * 0.9f)
    g_k[s] = (int)floorf(__int2float_rn(g_posCnt[s]) * 0.9f);
    int off = sstart[s];
    for (int c = 0; c < numChunks; c++) {
        int v = g_hist[c * NSEG + s];
        g_hist[c * NSEG + s] = off;
        off += v;
    }
}

// ---------------- stable counting-sort scatter (block multisplit) ----------------
__global__ __launch_bounds__(256) void k_scatter(const int* __restrict__ pos,
                                                 const int* __restrict__ neg,
                                                 const int* __restrict__ nb, int E, int T) {
    __shared__ int cnt[NSEG];
    __shared__ int wcnt[8][NSEG];
    int tid = threadIdx.x, w = tid >> 5, lane = tid & 31;
    int chunk = blockIdx.x;
    if (tid < NSEG) cnt[tid] = g_hist[chunk * NSEG + tid];
    __syncthreads();
#pragma unroll
    for (int r = 0; r < CH / 256; r++) {
        int e = chunk * CH + r * 256 + tid;
        bool valid = e < T;
        int seg = 0, src = 0, dst = 0;
        unsigned long long pk = 0;
        if (valid) {
            if (e < E) { src = pos[e]; dst = pos[E + e]; }
            else       { src = neg[e - E]; dst = neg[E + e - E]; }
            seg = nb[src];
            pk = (unsigned long long)(unsigned)src
               | ((unsigned long long)(unsigned)dst << 16)
               | ((unsigned long long)(e < E ? 1u : 0u) << 32);
        }
        for (int i = tid; i < 8 * NSEG; i += 256) ((int*)wcnt)[i] = 0;
        __syncthreads();
        unsigned m = __match_any_sync(0xffffffffu, valid ? seg : (256 + lane));
        int rank = __popc(m & ((1u << lane) - 1u));
        if (valid && rank == 0) wcnt[w][seg] = __popc(m);
        __syncthreads();
        if (valid) {
            int pre = 0;
#pragma unroll
            for (int ww = 0; ww < 8; ww++) if (ww < w) pre += wcnt[ww][seg];
            g_pack[cnt[seg] + pre + rank] = pk;
        }
        __syncthreads();
        if (tid < NSEG) {
            int tt = 0;
#pragma unroll
            for (int ww = 0; ww < 8; ww++) tt += wcnt[ww][tid];
            cnt[tid] += tt;
        }
        __syncthreads();
    }
}

// ---------------- per-edge MLP: warp per edge ----------------
__global__ __launch_bounds__(256) void k_mlp(const float* __restrict__ W1,
                                             const float* __restrict__ b1,
                                             const float* __restrict__ lng,
                                             const float* __restrict__ lnb,
                                             const float* __restrict__ W2,
                                             const float* __restrict__ b2, int T) {
    int lane = threadIdx.x & 31;
    int gw = (blockIdx.x * blockDim.x + threadIdx.x) >> 5;
    int nw = (gridDim.x * blockDim.x) >> 5;
    int j = lane * 4;
    float4 wL = *(const float4*)&W1[64 * H2 + j];
    float4 bb = *(const float4*)&b1[j];
    float4 g4 = *(const float4*)&lng[j];
    float4 be = *(const float4*)&lnb[j];
    float4 w2 = *(const float4*)&W2[j];
    float b2v = b2[0];
    for (int t = gw; t < T; t += nw) {
        unsigned long long pk = g_pack[t];
        int src = (int)(pk & 0xffffull);
        int dst = (int)((pk >> 16) & 0xffffull);
        float conn = (float)((pk >> 32) & 1ull);
        float4 a = *(const float4*)&g_P[src * H2 + j];
        float4 c = *(const float4*)&g_P[dst * H2 + j];
        float x0 = a.x + c.x + conn * wL.x + bb.x;
        float x1 = a.y + c.y + conn * wL.y + bb.y;
        float x2 = a.z + c.z + conn * wL.z + bb.z;
        float x3 = a.w + c.w + conn * wL.w + bb.w;
        float s = x0 + x1 + x2 + x3;
        float q = x0 * x0 + x1 * x1 + x2 * x2 + x3 * x3;
#pragma unroll
        for (int o = 16; o; o >>= 1) {
            s += __shfl_xor_sync(0xffffffffu, s, o);
            q += __shfl_xor_sync(0xffffffffu, q, o);
        }
        float mu = s * (1.0f / 128.0f);
        float var = q * (1.0f / 128.0f) - mu * mu;
        float rs = rsqrtf(var + 1e-5f);
        float y0 = fmaxf((x0 - mu) * rs * g4.x + be.x, 0.0f);
        float y1 = fmaxf((x1 - mu) * rs * g4.y + be.y, 0.0f);
        float y2 = fmaxf((x2 - mu) * rs * g4.z + be.z, 0.0f);
        float y3 = fmaxf((x3 - mu) * rs * g4.w + be.w, 0.0f);
        float p = y0 * w2.x + y1 * w2.y + y2 * w2.z + y3 * w2.w;
#pragma unroll
        for (int o = 16; o; o >>= 1) p += __shfl_xor_sync(0xffffffffu, p, o);
        if (lane == 0) {
            float logit = p + b2v;
            unsigned u = __float_as_uint(logit);
            u ^= (u & 0x80000000u) ? 0xffffffffu : 0x80000000u;
            g_ulog[t] = u;
        }
    }
}

// ---------------- radix select: k-th largest per segment ----------------
__global__ __launch_bounds__(256) void k_select() {
    int g = blockIdx.x;
    __shared__ int hist[256];
    __shared__ int s_chosen, s_kneed;
    int start = g_segStart[g];
    int cnt = g_segCnt[g];
    int k = g_k[g];
    if (k > cnt) k = cnt;
    if (k <= 0 || cnt <= 0) {
        if (threadIdx.x == 0) { g_thr[g] = 0xffffffffu; g_rem[g] = 0; }
        return;
    }
    unsigned pref = 0;
    int kneed = k;
    for (int pass = 0; pass < 4; pass++) {
        int shift = 24 - 8 * pass;
        for (int i = threadIdx.x; i < 256; i += blockDim.x) hist[i] = 0;
        __syncthreads();
        unsigned hi_mask = (pass == 0) ? 0u : (0xffffffffu << (shift + 8));
        for (int i = threadIdx.x; i < cnt; i += blockDim.x) {
            unsigned u = g_ulog[start + i];
            if (pass == 0 || (u & hi_mask) == pref)
                atomicAdd(&hist[(u >> shift) & 255], 1);
        }
        __syncthreads();
        if (threadIdx.x == 0) {
            int cum = 0, b = 255;
            for (; b >= 0; b--) {
                cum += hist[b];
                if (cum >= kneed) break;
            }
            if (b < 0) b = 0;  // safety
            s_chosen = b;
            s_kneed = kneed - (cum - hist[b]);
        }
        __syncthreads();
        kneed = s_kneed;
        pref |= ((unsigned)s_chosen) << shift;
        __syncthreads();
    }
    if (threadIdx.x == 0) { g_thr[g] = pref; g_rem[g] = kneed; }
}

// ---------------- final: mask / weight / node_mask, stable tie-break ----------------
__global__ __launch_bounds__(1024) void k_final(float* __restrict__ outMask,
                                                float* __restrict__ outW,
                                                float* __restrict__ outNM) {
    int g = blockIdx.x;
    int start = g_segStart[g];
    int cnt = g_segCnt[g];
    unsigned thr = g_thr[g];
    int rem = g_rem[g];
    __shared__ int warpTot[32];
    __shared__ int warpPre[32];
    __shared__ int s_base, s_rtot;
    int tid = threadIdx.x, w = tid >> 5, lane = tid & 31;
    if (tid == 0) s_base = 0;
    __syncthreads();
    for (int base = 0; base < cnt; base += 1024) {
        int i = base + tid;
        bool valid = i < cnt;
        unsigned u = 0;
        if (valid) u = g_ulog[start + i];
        bool gt = valid && (u > thr);
        bool eq = valid && (u == thr);
        unsigned bal = __ballot_sync(0xffffffffu, eq);
        int wpre = __popc(bal & ((1u << lane) - 1u));
        if (lane == 0) warpTot[w] = __popc(bal);
        __syncthreads();
        if (w == 0) {
            int v = warpTot[lane];
            int incl = v;
#pragma unroll
            for (int o = 1; o < 32; o <<= 1) {
                int t2 = __shfl_up_sync(0xffffffffu, incl, o);
                if (lane >= o) incl += t2;
            }
            warpPre[lane] = incl - v;
            if (lane == 31) s_rtot = incl;
        }
        __syncthreads();
        if (valid) {
            int eqrank = s_base + warpPre[w] + wpre;
            bool sel = gt || (eq && (eqrank < rem));
            int t = start + i;
            outMask[t] = sel ? 1.0f : 0.0f;
            unsigned fb = (u & 0x80000000u) ? (u ^ 0x80000000u) : ~u;
            outW[t] = sel ? __uint_as_float(fb) : 0.0f;
            if (sel) {
                unsigned long long pk = g_pack[t];
                outNM[(int)(pk & 0xffffull)] = 1.0f;
                outNM[(int)((pk >> 16) & 0xffffull)] = 1.0f;
            }
        }
        __syncthreads();
        if (tid == 0) s_base += s_rtot;
        __syncthreads();
    }
}

// ---------------- launch ----------------
extern "C" void kernel_launch(void* const* d_in, const int* in_sizes, int n_in,
                              void* d_out, int out_size) {
    const float* h   = (const float*)d_in[0];
    const float* W1  = (const float*)d_in[1];
    const float* b1  = (const float*)d_in[2];
    const float* lng = (const float*)d_in[3];
    const float* lnb = (const float*)d_in[4];
    const float* W2  = (const float*)d_in[5];
    const float* b2  = (const float*)d_in[6];
    const int* pos   = (const int*)d_in[7];
    const int* neg   = (const int*)d_in[8];
    const int* nb    = (const int*)d_in[9];

    int N = in_sizes[9];
    int E = in_sizes[7] / 2;
    int T = 2 * E;
    int numChunks = (T + CH - 1) / CH;

    float* outMask = (float*)d_out;
    float* outW    = outMask + T;
    float* outNM   = outW + T;

    k_zero<<<(N + 255) / 256, 256>>>(outNM, N);
    k_gemmP<<<256, 256>>>(h, W1, N);
    k_hist<<<numChunks, 256>>>(pos, neg, nb, E, T);
    k_scan<<<1, NSEG>>>(numChunks);
    k_scatter<<<numChunks, 256>>>(pos, neg, nb, E, T);
    k_mlp<<<2048, 256>>>(W1, b1, lng, lnb, W2, b2, T);
    k_select<<<NSEG, 256>>>();
    k_final<<<NSEG, 1024>>>(outMask, outW, outNM);
    (void)n_in; (void)out_size;
}

// round 2
// speedup vs baseline: 1.3512x; 1.3512x over previous
#include <cuda_runtime.h>
#include <cstdint>

#define HID 64
#define H2  128
#define NSEG 64
#define CH 1024
#define MAXN 50048
#define MAXT 1600512
#define MAXCHUNKS 1600
#define SS 8
#define FS 8

// ---------------- device scratch ----------------
__device__ float g_P[MAXN * H2];                 // 25.6 MB  h @ W1[:64,:]
__device__ unsigned long long g_pack[MAXT];      // src | dst<<16 | conn<<32 | seg<<33
__device__ unsigned g_ulog[MAXT];                // order-preserving uint32 logits
__device__ int g_hist[MAXCHUNKS * NSEG];
__device__ int g_posCnt[NSEG];
__device__ int g_segCnt[NSEG];
__device__ int g_segStart[NSEG + 1];
__device__ unsigned g_pref[NSEG];
__device__ int g_kneed[NSEG];
__device__ int g_selH[NSEG * 256];
__device__ int g_eqCnt[NSEG * FS];

// ---------------- zero ----------------
__global__ void k_zero(float* outNM, int N) {
    int i = blockIdx.x * blockDim.x + threadIdx.x;
    if (i < N) outNM[i] = 0.0f;
    if (i < NSEG * 256) g_selH[i] = 0;
    if (i < NSEG) { g_posCnt[i] = 0; g_segCnt[i] = 0; }
}

// ---------------- P = h @ W1[:64,:]  with 8-node register blocking ----------------
__global__ __launch_bounds__(256) void k_gemmP(const float* __restrict__ h,
                                               const float* __restrict__ W1, int N) {
    __shared__ float Ws[HID][H2];
    int tid = threadIdx.x;
    for (int i = tid; i < HID * H2; i += 256) Ws[i / H2][i % H2] = W1[i];
    __syncthreads();
    int w = tid >> 5, lane = tid & 31;
    int j = lane * 4;
    int totalWarps = gridDim.x * 8;
    for (int n0 = (blockIdx.x * 8 + w) * 8; n0 < N; n0 += totalWarps * 8) {
        float h0[8], h1[8];
#pragma unroll
        for (int m = 0; m < 8; m++) {
            int nm = n0 + m;
            if (nm < N) { h0[m] = h[nm * HID + lane]; h1[m] = h[nm * HID + 32 + lane]; }
            else { h0[m] = 0.f; h1[m] = 0.f; }
        }
        float4 acc[8];
#pragma unroll
        for (int m = 0; m < 8; m++) acc[m] = make_float4(0.f, 0.f, 0.f, 0.f);
#pragma unroll
        for (int k = 0; k < 64; k++) {
            float4 wv = *(const float4*)&Ws[k][j];
#pragma unroll
            for (int m = 0; m < 8; m++) {
                float hv = __shfl_sync(0xffffffffu, (k < 32) ? h0[m] : h1[m], k & 31);
                acc[m].x += hv * wv.x; acc[m].y += hv * wv.y;
                acc[m].z += hv * wv.z; acc[m].w += hv * wv.w;
            }
        }
#pragma unroll
        for (int m = 0; m < 8; m++)
            if (n0 + m < N) *(float4*)&g_P[(n0 + m) * H2 + j] = acc[m];
    }
}

// ---------------- per-chunk seg histograms + seg totals ----------------
__global__ __launch_bounds__(256) void k_hist(const int* __restrict__ pos,
                                              const int* __restrict__ neg,
                                              const int* __restrict__ nb, int E, int T) {
    __shared__ int sh[NSEG];
    __shared__ int shp[NSEG];
    int tid = threadIdx.x;
    if (tid < NSEG) { sh[tid] = 0; shp[tid] = 0; }
    __syncthreads();
    int chunk = blockIdx.x;
    int base = chunk * CH;
    for (int i = tid; i < CH; i += 256) {
        int e = base + i;
        if (e < T) {
            int src = (e < E) ? pos[e] : neg[e - E];
            int s = nb[src];
            atomicAdd(&sh[s], 1);
            if (e < E) atomicAdd(&shp[s], 1);
        }
    }
    __syncthreads();
    if (tid < NSEG) {
        g_hist[chunk * NSEG + tid] = sh[tid];
        if (shp[tid]) atomicAdd(&g_posCnt[tid], shp[tid]);
        if (sh[tid]) atomicAdd(&g_segCnt[tid], sh[tid]);
    }
}

// ---------------- tiny cross-seg scan + select state init ----------------
__global__ void k_scanB() {
    __shared__ int sstart[NSEG + 1];
    int s = threadIdx.x;  // 64 threads
    if (s == 0) {
        int acc = 0;
        for (int i = 0; i < NSEG; i++) { sstart[i] = acc; acc += g_segCnt[i]; }
        sstart[NSEG] = acc;
    }
    __syncthreads();
    g_segStart[s] = sstart[s];
    if (s == 0) g_segStart[NSEG] = sstart[NSEG];
    int k = (int)floorf(__int2float_rn(g_posCnt[s]) * 0.9f);
    int cnt = g_segCnt[s];
    if (k > cnt) k = cnt;
    if (k < 0) k = 0;
    g_pref[s] = 0u;
    g_kneed[s] = k;
}

// ---------------- parallel per-seg chunk prefix ----------------
__global__ __launch_bounds__(256) void k_scanC(int numChunks) {
    __shared__ int sh[256];
    int s = blockIdx.x;
    int tid = threadIdx.x;
    int q = (numChunks + 255) / 256;
    int c0 = tid * q;
    int c1 = min(numChunks, c0 + q);
    int mySum = 0;
    for (int c = c0; c < c1; c++) mySum += g_hist[c * NSEG + s];
    sh[tid] = mySum;
    __syncthreads();
    for (int off = 1; off < 256; off <<= 1) {
        int v = (tid >= off) ? sh[tid - off] : 0;
        __syncthreads();
        sh[tid] += v;
        __syncthreads();
    }
    int off = g_segStart[s] + sh[tid] - mySum;
    for (int c = c0; c < c1; c++) {
        int v = g_hist[c * NSEG + s];
        g_hist[c * NSEG + s] = off;
        off += v;
    }
}

// ---------------- stable counting-sort scatter ----------------
__global__ __launch_bounds__(256) void k_scatter(const int* __restrict__ pos,
                                                 const int* __restrict__ neg,
                                                 const int* __restrict__ nb, int E, int T) {
    __shared__ int cnt[NSEG];
    __shared__ int wcnt[8][NSEG];
    int tid = threadIdx.x, w = tid >> 5, lane = tid & 31;
    int chunk = blockIdx.x;
    if (tid < NSEG) cnt[tid] = g_hist[chunk * NSEG + tid];
#pragma unroll
    for (int r = 0; r < CH / 256; r++) {
        int e = chunk * CH + r * 256 + tid;
        bool valid = e < T;
        int seg = 0;
        unsigned long long pk = 0;
        if (valid) {
            int src, dst;
            if (e < E) { src = pos[e]; dst = pos[E + e]; }
            else       { src = neg[e - E]; dst = neg[E + (e - E)]; }
            seg = nb[src];
            pk = (unsigned long long)(unsigned)src
               | ((unsigned long long)(unsigned)dst << 16)
               | ((unsigned long long)(e < E ? 1u : 0u) << 32)
               | ((unsigned long long)(unsigned)seg << 33);
        }
        for (int i = tid; i < 8 * NSEG; i += 256) ((int*)wcnt)[i] = 0;
        __syncthreads();
        unsigned m = __match_any_sync(0xffffffffu, valid ? seg : (256 + lane));
        int rank = __popc(m & ((1u << lane) - 1u));
        if (valid && rank == 0) wcnt[w][seg] = __popc(m);
        __syncthreads();
        // 64 threads convert per-warp counts into absolute bases, bump cnt
        if (tid < NSEG) {
            int acc = cnt[tid];
#pragma unroll
            for (int ww = 0; ww < 8; ww++) {
                int v = wcnt[ww][tid];
                wcnt[ww][tid] = acc;
                acc += v;
            }
            cnt[tid] = acc;
        }
        __syncthreads();
        if (valid) g_pack[wcnt[w][seg] + rank] = pk;
        __syncthreads();
    }
}

// ---------------- per-edge MLP: 16 lanes/edge, 2 edges/warp ----------------
__global__ __launch_bounds__(256) void k_mlp(const float* __restrict__ W1,
                                             const float* __restrict__ b1,
                                             const float* __restrict__ lng,
                                             const float* __restrict__ lnb,
                                             const float* __restrict__ W2,
                                             const float* __restrict__ b2, int T) {
    int lane = threadIdx.x & 31;
    int half = lane >> 4, hl = lane & 15;
    int gw = (blockIdx.x * blockDim.x + threadIdx.x) >> 5;
    int nw = (gridDim.x * blockDim.x) >> 5;
    int j = hl * 8;
    float4 wL0 = *(const float4*)&W1[64 * H2 + j];
    float4 wL1 = *(const float4*)&W1[64 * H2 + j + 4];
    float4 bb0 = *(const float4*)&b1[j];
    float4 bb1 = *(const float4*)&b1[j + 4];
    float4 g0 = *(const float4*)&lng[j];
    float4 g1 = *(const float4*)&lng[j + 4];
    float4 e0 = *(const float4*)&lnb[j];
    float4 e1 = *(const float4*)&lnb[j + 4];
    float4 w20 = *(const float4*)&W2[j];
    float4 w21 = *(const float4*)&W2[j + 4];
    float b2v = b2[0];
    for (int t2 = gw * 2; t2 < T; t2 += nw * 2) {
        int t = t2 + half;   // T even, so t < T always
        unsigned long long pk = g_pack[t];
        int src = (int)(pk & 0xffffull);
        int dst = (int)((pk >> 16) & 0xffffull);
        float conn = (float)((pk >> 32) & 1ull);
        int seg = (int)((pk >> 33) & 63ull);
        const float4* ps = (const float4*)&g_P[src * H2 + j];
        const float4* pd = (const float4*)&g_P[dst * H2 + j];
        float4 a0 = ps[0], a1 = ps[1];
        float4 c0 = pd[0], c1 = pd[1];
        float x0 = a0.x + c0.x + conn * wL0.x + bb0.x;
        float x1 = a0.y + c0.y + conn * wL0.y + bb0.y;
        float x2 = a0.z + c0.z + conn * wL0.z + bb0.z;
        float x3 = a0.w + c0.w + conn * wL0.w + bb0.w;
        float x4 = a1.x + c1.x + conn * wL1.x + bb1.x;
        float x5 = a1.y + c1.y + conn * wL1.y + bb1.y;
        float x6 = a1.z + c1.z + conn * wL1.z + bb1.z;
        float x7 = a1.w + c1.w + conn * wL1.w + bb1.w;
        float s = x0 + x1 + x2 + x3 + x4 + x5 + x6 + x7;
        float q = x0*x0 + x1*x1 + x2*x2 + x3*x3 + x4*x4 + x5*x5 + x6*x6 + x7*x7;
#pragma unroll
        for (int o = 8; o; o >>= 1) {
            s += __shfl_xor_sync(0xffffffffu, s, o);
            q += __shfl_xor_sync(0xffffffffu, q, o);
        }
        float mu = s * (1.0f / 128.0f);
        float var = q * (1.0f / 128.0f) - mu * mu;
        float rs = rsqrtf(var + 1e-5f);
        float p =
          fmaxf((x0 - mu) * rs * g0.x + e0.x, 0.0f) * w20.x
        + fmaxf((x1 - mu) * rs * g0.y + e0.y, 0.0f) * w20.y
        + fmaxf((x2 - mu) * rs * g0.z + e0.z, 0.0f) * w20.z
        + fmaxf((x3 - mu) * rs * g0.w + e0.w, 0.0f) * w20.w
        + fmaxf((x4 - mu) * rs * g1.x + e1.x, 0.0f) * w21.x
        + fmaxf((x5 - mu) * rs * g1.y + e1.y, 0.0f) * w21.y
        + fmaxf((x6 - mu) * rs * g1.z + e1.z, 0.0f) * w21.z
        + fmaxf((x7 - mu) * rs * g1.w + e1.w, 0.0f) * w21.w;
#pragma unroll
        for (int o = 8; o; o >>= 1) p += __shfl_xor_sync(0xffffffffu, p, o);
        if (hl == 0) {
            float logit = p + b2v;
            unsigned u = __float_as_uint(logit);
            u ^= (u & 0x80000000u) ? 0xffffffffu : 0x80000000u;
            g_ulog[t] = u;
            atomicAdd(&g_selH[seg * 256 + (int)(u >> 24)], 1);  // fused pass-0 hist
        }
    }
}

// ---------------- striped radix-select passes 1..3 ----------------
__global__ __launch_bounds__(256) void k_selHist(int p) {
    __shared__ int sh[256];
    int seg = blockIdx.x >> 3, stripe = blockIdx.x & 7;
    if (g_kneed[seg] <= 0) return;
    int start = g_segStart[seg], cnt = g_segCnt[seg];
    int shift = 24 - 8 * p;
    unsigned hiMask = 0xffffffffu << (shift + 8);
    unsigned pref = g_pref[seg];
    int tid = threadIdx.x;
    sh[tid] = 0;
    __syncthreads();
    int sl = (cnt + SS - 1) / SS;
    int lo = stripe * sl;
    int hi = min(cnt, lo + sl);
    for (int i = lo + tid; i < hi; i += 256) {
        unsigned u = g_ulog[start + i];
        if ((u & hiMask) == pref) atomicAdd(&sh[(u >> shift) & 255], 1);
    }
    __syncthreads();
    if (sh[tid]) atomicAdd(&g_selH[seg * 256 + tid], sh[tid]);
}

__global__ __launch_bounds__(256) void k_selPick(int p) {
    __shared__ int sh[256];
    int g = blockIdx.x;
    int tid = threadIdx.x;
    sh[tid] = g_selH[g * 256 + tid];
    g_selH[g * 256 + tid] = 0;  // ready for next pass / next replay
    __syncthreads();
    if (tid == 0) {
        int shift = 24 - 8 * p;
        int kneed = g_kneed[g];
        if (kneed > 0) {
            int cum = 0, b = 255;
            for (; b >= 0; b--) {
                cum += sh[b];
                if (cum >= kneed) break;
            }
            if (b < 0) b = 0;
            g_pref[g] |= ((unsigned)b) << shift;
            g_kneed[g] = kneed - (cum - sh[b]);
        } else {
            g_pref[g] |= 0xffu << shift;  // thr -> 0xFFFFFFFF, selects nothing
        }
    }
}

// ---------------- final stage: non-eq outputs + per-stripe eq counts ----------------
__global__ __launch_bounds__(256) void f_count(float* __restrict__ outMask,
                                               float* __restrict__ outW,
                                               float* __restrict__ outNM) {
    __shared__ int s_eq;
    int seg = blockIdx.x >> 3, stripe = blockIdx.x & 7;
    int start = g_segStart[seg], cnt = g_segCnt[seg];
    unsigned thr = g_pref[seg];
    int tid = threadIdx.x, lane = tid & 31;
    if (tid == 0) s_eq = 0;
    __syncthreads();
    int sl = (cnt + FS - 1) / FS;
    int lo = stripe * sl;
    int hi = min(cnt, lo + sl);
    int myEq = 0;
    for (int i = lo + tid; i < hi; i += 256) {
        int t = start + i;
        unsigned u = g_ulog[t];
        if (u == thr) { myEq++; continue; }
        bool gt = u > thr;
        outMask[t] = gt ? 1.0f : 0.0f;
        if (gt) {
            unsigned fb = (u & 0x80000000u) ? (u ^ 0x80000000u) : ~u;
            outW[t] = __uint_as_float(fb);
            unsigned long long pk = g_pack[t];
            outNM[(int)(pk & 0xffffull)] = 1.0f;
            outNM[(int)((pk >> 16) & 0xffffull)] = 1.0f;
        } else {
            outW[t] = 0.0f;
        }
    }
    unsigned bal = __ballot_sync(0xffffffffu, myEq > 0);
    (void)bal;
#pragma unroll
    for (int o = 16; o; o >>= 1) myEq += __shfl_xor_sync(0xffffffffu, myEq, o);
    if (lane == 0 && myEq) atomicAdd(&s_eq, myEq);
    __syncthreads();
    if (tid == 0) g_eqCnt[seg * FS + stripe] = s_eq;
}

__global__ void f_scan() {
    int s = threadIdx.x;  // 64 threads
    int base = 0;
#pragma unroll
    for (int st = 0; st < FS; st++) {
        int v = g_eqCnt[s * FS + st];
        g_eqCnt[s * FS + st] = base;
        base += v;
    }
}

// ---------------- mark eq elements with stable rank ----------------
__global__ __launch_bounds__(256) void f_mark(float* __restrict__ outMask,
                                              float* __restrict__ outW,
                                              float* __restrict__ outNM) {
    __shared__ int wTot[8];
    __shared__ int s_tot;
    __shared__ int s_base;
    int seg = blockIdx.x >> 3, stripe = blockIdx.x & 7;
    int start = g_segStart[seg], cnt = g_segCnt[seg];
    unsigned thr = g_pref[seg];
    int rem = g_kneed[seg];
    int stripeBase = g_eqCnt[seg * FS + stripe];
    int tid = threadIdx.x, w = tid >> 5, lane = tid & 31;
    if (tid == 0) s_base = 0;
    __syncthreads();
    int sl = (cnt + FS - 1) / FS;
    int lo = stripe * sl;
    int hi = min(cnt, lo + sl);
    for (int i0 = lo; i0 < hi; i0 += 256) {
        int i = i0 + tid;
        bool eq = false;
        unsigned u = 0;
        if (i < hi) { u = g_ulog[start + i]; eq = (u == thr); }
        unsigned bal = __ballot_sync(0xffffffffu, eq);
        int wpre = __popc(bal & ((1u << lane) - 1u));
        if (lane == 0) wTot[w] = __popc(bal);
        __syncthreads();
        if (tid == 0) {
            int acc = 0;
#pragma unroll
            for (int ww = 0; ww < 8; ww++) { int v = wTot[ww]; wTot[ww] = acc; acc += v; }
            s_tot = acc;
        }
        __syncthreads();
        if (eq) {
            int rank = stripeBase + s_base + wTot[w] + wpre;
            bool sel = rank < rem;
            int t = start + i;
            outMask[t] = sel ? 1.0f : 0.0f;
            if (sel) {
                unsigned fb = (u & 0x80000000u) ? (u ^ 0x80000000u) : ~u;
                outW[t] = __uint_as_float(fb);
                unsigned long long pk = g_pack[t];
                outNM[(int)(pk & 0xffffull)] = 1.0f;
                outNM[(int)((pk >> 16) & 0xffffull)] = 1.0f;
            } else {
                outW[t] = 0.0f;
            }
        }
        __syncthreads();
        if (tid == 0) s_base += s_tot;
        __syncthreads();
    }
}

// ---------------- launch ----------------
extern "C" void kernel_launch(void* const* d_in, const int* in_sizes, int n_in,
                              void* d_out, int out_size) {
    const float* h   = (const float*)d_in[0];
    const float* W1  = (const float*)d_in[1];
    const float* b1  = (const float*)d_in[2];
    const float* lng = (const float*)d_in[3];
    const float* lnb = (const float*)d_in[4];
    const float* W2  = (const float*)d_in[5];
    const float* b2  = (const float*)d_in[6];
    const int* pos   = (const int*)d_in[7];
    const int* neg   = (const int*)d_in[8];
    const int* nb    = (const int*)d_in[9];

    int N = in_sizes[9];
    int E = in_sizes[7] / 2;
    int T = 2 * E;
    int numChunks = (T + CH - 1) / CH;

    float* outMask = (float*)d_out;
    float* outW    = outMask + T;
    float* outNM   = outW + T;

    int zn = N > NSEG * 256 ? N : NSEG * 256;
    k_zero<<<(zn + 255) / 256, 256>>>(outNM, N);
    k_gemmP<<<296, 256>>>(h, W1, N);
    k_hist<<<numChunks, 256>>>(pos, neg, nb, E, T);
    k_scanB<<<1, NSEG>>>();
    k_scanC<<<NSEG, 256>>>(numChunks);
    k_scatter<<<numChunks, 256>>>(pos, neg, nb, E, T);
    k_mlp<<<2048, 256>>>(W1, b1, lng, lnb, W2, b2, T);
    k_selPick<<<NSEG, 256>>>(0);
    k_selHist<<<NSEG * SS, 256>>>(1);
    k_selPick<<<NSEG, 256>>>(1);
    k_selHist<<<NSEG * SS, 256>>>(2);
    k_selPick<<<NSEG, 256>>>(2);
    k_selHist<<<NSEG * SS, 256>>>(3);
    k_selPick<<<NSEG, 256>>>(3);
    f_count<<<NSEG * FS, 256>>>(outMask, outW, outNM);
    f_scan<<<1, NSEG>>>();
    f_mark<<<NSEG * FS, 256>>>(outMask, outW, outNM);
    (void)n_in; (void)out_size;
}

// round 3
// speedup vs baseline: 1.3815x; 1.0225x over previous
#include <cuda_runtime.h>
#include <cstdint>

#define HID 64
#define H2  128
#define NSEG 64
#define CH 1024
#define MAXN 50048
#define MAXT 1600512
#define MAXCHUNKS 1600
#define NSM 152
#define WAVES 3
#define CAP 10240
#define ECAP 2048

// ---------------- device scratch ----------------
__device__ float g_P[MAXN * H2];                 // 25.6 MB  h @ W1[:64,:]
__device__ unsigned long long g_pack[MAXT];      // src | dst<<16 | conn<<32 | seg<<33
__device__ unsigned g_ulog[MAXT];                // order-preserving uint32 logits
__device__ int g_hist[MAXCHUNKS * NSEG];
__device__ int g_posCnt[NSEG];
__device__ int g_segCnt[NSEG];
__device__ int g_segStart[NSEG];
__device__ unsigned g_thr[NSEG];
__device__ int g_rem[NSEG];
__device__ int g_selH16[NSEG * 65536];           // 16 MB 16-bit histograms
__device__ int g_eqN[NSEG];
__device__ int g_eqIdx[NSEG * ECAP];

__device__ __forceinline__ float unflip(unsigned u) {
    unsigned fb = (u & 0x80000000u) ? (u ^ 0x80000000u) : ~u;
    return __uint_as_float(fb);
}

// ---------------- zero all per-replay atomic state ----------------
__global__ void k_zero(float* outNM, int N) {
    int i = blockIdx.x * blockDim.x + threadIdx.x;
    if (i < NSEG * 65536) g_selH16[i] = 0;
    if (i < N) outNM[i] = 0.0f;
    if (i < NSEG) { g_posCnt[i] = 0; g_segCnt[i] = 0; g_eqN[i] = 0; }
}

// ---------------- P = h @ W1[:64,:]  8-node register blocking ----------------
__global__ __launch_bounds__(256) void k_gemmP(const float* __restrict__ h,
                                               const float* __restrict__ W1, int N) {
    __shared__ float Ws[HID][H2];
    int tid = threadIdx.x;
    for (int i = tid; i < HID * H2; i += 256) Ws[i / H2][i % H2] = W1[i];
    __syncthreads();
    int w = tid >> 5, lane = tid & 31;
    int j = lane * 4;
    int totalWarps = gridDim.x * 8;
    for (int n0 = (blockIdx.x * 8 + w) * 8; n0 < N; n0 += totalWarps * 8) {
        float h0[8], h1[8];
#pragma unroll
        for (int m = 0; m < 8; m++) {
            int nm = n0 + m;
            if (nm < N) { h0[m] = h[nm * HID + lane]; h1[m] = h[nm * HID + 32 + lane]; }
            else { h0[m] = 0.f; h1[m] = 0.f; }
        }
        float4 acc[8];
#pragma unroll
        for (int m = 0; m < 8; m++) acc[m] = make_float4(0.f, 0.f, 0.f, 0.f);
#pragma unroll
        for (int k = 0; k < 64; k++) {
            float4 wv = *(const float4*)&Ws[k][j];
#pragma unroll
            for (int m = 0; m < 8; m++) {
                float hv = __shfl_sync(0xffffffffu, (k < 32) ? h0[m] : h1[m], k & 31);
                acc[m].x += hv * wv.x; acc[m].y += hv * wv.y;
                acc[m].z += hv * wv.z; acc[m].w += hv * wv.w;
            }
        }
#pragma unroll
        for (int m = 0; m < 8; m++)
            if (n0 + m < N) *(float4*)&g_P[(n0 + m) * H2 + j] = acc[m];
    }
}

// ---------------- per-chunk seg histograms + seg totals ----------------
__global__ __launch_bounds__(256) void k_hist(const int* __restrict__ pos,
                                              const int* __restrict__ neg,
                                              const int* __restrict__ nb, int E, int T) {
    __shared__ int sh[NSEG];
    __shared__ int shp[NSEG];
    int tid = threadIdx.x;
    if (tid < NSEG) { sh[tid] = 0; shp[tid] = 0; }
    __syncthreads();
    int base = blockIdx.x * CH;
    for (int i = tid; i < CH; i += 256) {
        int e = base + i;
        if (e < T) {
            int src = (e < E) ? pos[e] : neg[e - E];
            int s = nb[src];
            atomicAdd(&sh[s], 1);
            if (e < E) atomicAdd(&shp[s], 1);
        }
    }
    __syncthreads();
    if (tid < NSEG) {
        g_hist[blockIdx.x * NSEG + tid] = sh[tid];
        if (shp[tid]) atomicAdd(&g_posCnt[tid], shp[tid]);
        if (sh[tid]) atomicAdd(&g_segCnt[tid], sh[tid]);
    }
}

// ---------------- per-seg chunk prefix (computes segStart too) ----------------
__global__ __launch_bounds__(256) void k_scanC(int numChunks) {
    __shared__ int sh[256];
    __shared__ int segc[NSEG];
    __shared__ int s_start;
    int s = blockIdx.x;
    int tid = threadIdx.x;
    if (tid < NSEG) segc[tid] = g_segCnt[tid];
    __syncthreads();
    if (tid == 0) {
        int acc = 0;
        for (int i = 0; i < s; i++) acc += segc[i];
        s_start = acc;
        g_segStart[s] = acc;
    }
    int q = (numChunks + 255) / 256;
    int c0 = tid * q;
    int c1 = min(numChunks, c0 + q);
    int mySum = 0;
    for (int c = c0; c < c1; c++) mySum += g_hist[c * NSEG + s];
    sh[tid] = mySum;
    __syncthreads();
    for (int off = 1; off < 256; off <<= 1) {
        int v = (tid >= off) ? sh[tid - off] : 0;
        __syncthreads();
        sh[tid] += v;
        __syncthreads();
    }
    int off = s_start + sh[tid] - mySum;
    for (int c = c0; c < c1; c++) {
        int v = g_hist[c * NSEG + s];
        g_hist[c * NSEG + s] = off;
        off += v;
    }
}

// ---------------- stable counting-sort scatter ----------------
__global__ __launch_bounds__(256) void k_scatter(const int* __restrict__ pos,
                                                 const int* __restrict__ neg,
                                                 const int* __restrict__ nb, int E, int T) {
    __shared__ int cnt[NSEG];
    __shared__ int wcnt[8][NSEG];
    int tid = threadIdx.x, w = tid >> 5, lane = tid & 31;
    int chunk = blockIdx.x;
    if (tid < NSEG) cnt[tid] = g_hist[chunk * NSEG + tid];
#pragma unroll
    for (int r = 0; r < CH / 256; r++) {
        int e = chunk * CH + r * 256 + tid;
        bool valid = e < T;
        int seg = 0;
        unsigned long long pk = 0;
        if (valid) {
            int src, dst;
            if (e < E) { src = pos[e]; dst = pos[E + e]; }
            else       { src = neg[e - E]; dst = neg[E + (e - E)]; }
            seg = nb[src];
            pk = (unsigned long long)(unsigned)src
               | ((unsigned long long)(unsigned)dst << 16)
               | ((unsigned long long)(e < E ? 1u : 0u) << 32)
               | ((unsigned long long)(unsigned)seg << 33);
        }
        for (int i = tid; i < 8 * NSEG; i += 256) ((int*)wcnt)[i] = 0;
        __syncthreads();
        unsigned m = __match_any_sync(0xffffffffu, valid ? seg : (256 + lane));
        int rank = __popc(m & ((1u << lane) - 1u));
        if (valid && rank == 0) wcnt[w][seg] = __popc(m);
        __syncthreads();
        if (tid < NSEG) {
            int acc = cnt[tid];
#pragma unroll
            for (int ww = 0; ww < 8; ww++) {
                int v = wcnt[ww][tid];
                wcnt[ww][tid] = acc;
                acc += v;
            }
            cnt[tid] = acc;
        }
        __syncthreads();
        if (valid) g_pack[wcnt[w][seg] + rank] = pk;
        __syncthreads();
    }
}

// ---------------- MLP: contiguous tiles, SM-affine swizzle, fused 16b hist ----------------
__global__ __launch_bounds__(256) void k_mlp(const float* __restrict__ W1,
                                             const float* __restrict__ b1,
                                             const float* __restrict__ lng,
                                             const float* __restrict__ lnb,
                                             const float* __restrict__ W2,
                                             const float* __restrict__ b2,
                                             int T, int MT) {
    int bid = blockIdx.x;
    int tile = (bid % NSM) * WAVES + (bid / NSM);
    int start = tile * MT;
    if (start >= T) return;
    int end = min(T, start + MT);
    int lane = threadIdx.x & 31;
    int half = lane >> 4, hl = lane & 15;
    int w = threadIdx.x >> 5;
    int j = hl * 8;
    float4 wL0 = *(const float4*)&W1[64 * H2 + j];
    float4 wL1 = *(const float4*)&W1[64 * H2 + j + 4];
    float4 bb0 = *(const float4*)&b1[j];
    float4 bb1 = *(const float4*)&b1[j + 4];
    float4 g0 = *(const float4*)&lng[j];
    float4 g1 = *(const float4*)&lng[j + 4];
    float4 e0 = *(const float4*)&lnb[j];
    float4 e1 = *(const float4*)&lnb[j + 4];
    float4 w20 = *(const float4*)&W2[j];
    float4 w21 = *(const float4*)&W2[j + 4];
    float b2v = b2[0];
#pragma unroll 2
    for (int t2 = start + w * 2; t2 < end; t2 += 16) {
        int t = t2 + half;
        unsigned long long pk = g_pack[t];
        int src = (int)(pk & 0xffffull);
        int dst = (int)((pk >> 16) & 0xffffull);
        float conn = (float)((pk >> 32) & 1ull);
        int seg = (int)((pk >> 33) & 63ull);
        const float4* ps = (const float4*)&g_P[src * H2 + j];
        const float4* pd = (const float4*)&g_P[dst * H2 + j];
        float4 a0 = ps[0], a1 = ps[1];
        float4 c0 = pd[0], c1 = pd[1];
        float x0 = a0.x + c0.x + conn * wL0.x + bb0.x;
        float x1 = a0.y + c0.y + conn * wL0.y + bb0.y;
        float x2 = a0.z + c0.z + conn * wL0.z + bb0.z;
        float x3 = a0.w + c0.w + conn * wL0.w + bb0.w;
        float x4 = a1.x + c1.x + conn * wL1.x + bb1.x;
        float x5 = a1.y + c1.y + conn * wL1.y + bb1.y;
        float x6 = a1.z + c1.z + conn * wL1.z + bb1.z;
        float x7 = a1.w + c1.w + conn * wL1.w + bb1.w;
        float s = x0 + x1 + x2 + x3 + x4 + x5 + x6 + x7;
        float q = x0*x0 + x1*x1 + x2*x2 + x3*x3 + x4*x4 + x5*x5 + x6*x6 + x7*x7;
#pragma unroll
        for (int o = 8; o; o >>= 1) {
            s += __shfl_xor_sync(0xffffffffu, s, o);
            q += __shfl_xor_sync(0xffffffffu, q, o);
        }
        float mu = s * (1.0f / 128.0f);
        float var = q * (1.0f / 128.0f) - mu * mu;
        float rs = rsqrtf(var + 1e-5f);
        float p =
          fmaxf((x0 - mu) * rs * g0.x + e0.x, 0.0f) * w20.x
        + fmaxf((x1 - mu) * rs * g0.y + e0.y, 0.0f) * w20.y
        + fmaxf((x2 - mu) * rs * g0.z + e0.z, 0.0f) * w20.z
        + fmaxf((x3 - mu) * rs * g0.w + e0.w, 0.0f) * w20.w
        + fmaxf((x4 - mu) * rs * g1.x + e1.x, 0.0f) * w21.x
        + fmaxf((x5 - mu) * rs * g1.y + e1.y, 0.0f) * w21.y
        + fmaxf((x6 - mu) * rs * g1.z + e1.z, 0.0f) * w21.z
        + fmaxf((x7 - mu) * rs * g1.w + e1.w, 0.0f) * w21.w;
#pragma unroll
        for (int o = 8; o; o >>= 1) p += __shfl_xor_sync(0xffffffffu, p, o);
        if (hl == 0) {
            float logit = p + b2v;
            unsigned u = __float_as_uint(logit);
            u ^= (u & 0x80000000u) ? 0xffffffffu : 0x80000000u;
            g_ulog[t] = u;
            atomicAdd(&g_selH16[(seg << 16) + (int)(u >> 16)], 1);
        }
    }
}

// ---------------- single-kernel exact select: bucket pick + 2 refinements ----------------
__global__ __launch_bounds__(256) void k_solve() {
    __shared__ int chunk[256];
    __shared__ int h8[256];
    __shared__ unsigned cand[CAP];
    __shared__ int s_n;
    __shared__ unsigned s_pref;
    __shared__ int s_kn;
    int g = blockIdx.x;
    int tid = threadIdx.x, w = tid >> 5, lane = tid & 31;
    int cnt = g_segCnt[g];
    int start = g_segStart[g];
    int k = (int)floorf(__int2float_rn(g_posCnt[g]) * 0.9f);
    if (k > cnt) k = cnt;
    if (k <= 0 || cnt <= 0) {
        if (tid == 0) { g_thr[g] = 0xffffffffu; g_rem[g] = 0; }
        return;
    }
    const int* H = &g_selH16[g << 16];
    // phase 1a: 256 chunk sums (warp-per-chunk, coalesced)
    for (int c = w; c < 256; c += 8) {
        int sm = 0;
#pragma unroll
        for (int i = 0; i < 8; i++) sm += H[c * 256 + i * 32 + lane];
#pragma unroll
        for (int o = 16; o; o >>= 1) sm += __shfl_xor_sync(0xffffffffu, sm, o);
        if (lane == 0) chunk[c] = sm;
    }
    __syncthreads();
    if (tid == 0) {
        int acc = 0, c = 255;
        for (; c > 0; c--) { acc += chunk[c]; if (acc >= k) break; }
        if (acc < k) acc += chunk[0];
        s_pref = (unsigned)c;
        s_kn = k - (acc - chunk[c]);
    }
    __syncthreads();
    int c16 = (int)s_pref;
    chunk[tid] = H[c16 * 256 + tid];
    __syncthreads();
    if (tid == 0) {
        int kn = s_kn, acc = 0, b = 255;
        for (; b > 0; b--) { acc += chunk[b]; if (acc >= kn) break; }
        if (acc < kn) acc += chunk[0];
        s_pref = (unsigned)(c16 * 256 + b);
        s_kn = kn - (acc - chunk[b]);
        s_n = 0;
    }
    h8[tid] = 0;
    __syncthreads();
    unsigned p16 = s_pref;
    // phase 2: compact matching values into smem + byte1 hist
    for (int i = tid; i < cnt; i += 256) {
        unsigned u = g_ulog[start + i];
        if ((u >> 16) == p16) {
            atomicAdd(&h8[(u >> 8) & 255], 1);
            int p = atomicAdd(&s_n, 1);
            if (p < CAP) cand[p] = u;
        }
    }
    __syncthreads();
    if (tid == 0) {
        int kn = s_kn, acc = 0, b = 255;
        for (; b > 0; b--) { acc += h8[b]; if (acc >= kn) break; }
        if (acc < kn) acc += h8[0];
        s_pref = (p16 << 8) | (unsigned)b;
        s_kn = kn - (acc - h8[b]);
    }
    __syncthreads();
    unsigned p24 = s_pref;
    int kn2 = s_kn;
    int n = s_n;
    h8[tid] = 0;
    __syncthreads();
    // phase 3: byte0 hist over candidates (smem fast path / global fallback)
    if (n <= CAP) {
        for (int i = tid; i < n; i += 256) {
            unsigned u = cand[i];
            if ((u >> 8) == p24) atomicAdd(&h8[u & 255], 1);
        }
    } else {
        for (int i = tid; i < cnt; i += 256) {
            unsigned u = g_ulog[start + i];
            if ((u >> 8) == p24) atomicAdd(&h8[u & 255], 1);
        }
    }
    __syncthreads();
    if (tid == 0) {
        int acc = 0, b = 255;
        for (; b > 0; b--) { acc += h8[b]; if (acc >= kn2) break; }
        if (acc < kn2) acc += h8[0];
        g_thr[g] = (p24 << 8) | (unsigned)b;
        g_rem[g] = kn2 - (acc - h8[b]);
    }
}

// ---------------- elementwise finalize (non-eq) + eq candidate capture ----------------
__global__ __launch_bounds__(256) void f_count(float* __restrict__ outMask,
                                               float* __restrict__ outW,
                                               float* __restrict__ outNM, int T) {
    int t = blockIdx.x * 256 + threadIdx.x;
    if (t >= T) return;
    unsigned long long pk = g_pack[t];
    int seg = (int)((pk >> 33) & 63ull);
    unsigned thr = g_thr[seg];
    unsigned u = g_ulog[t];
    if (u == thr) {
        int p = atomicAdd(&g_eqN[seg], 1);
        if (p < ECAP) g_eqIdx[seg * ECAP + p] = t;
    } else {
        bool gt = u > thr;
        outMask[t] = gt ? 1.0f : 0.0f;
        if (gt) {
            outW[t] = unflip(u);
            outNM[(int)(pk & 0xffffull)] = 1.0f;
            outNM[(int)((pk >> 16) & 0xffffull)] = 1.0f;
        } else {
            outW[t] = 0.0f;
        }
    }
}

// ---------------- tie-break: sort eq candidates by index, take first rem ----------------
__global__ __launch_bounds__(256) void f_mark(float* __restrict__ outMask,
                                              float* __restrict__ outW,
                                              float* __restrict__ outNM) {
    __shared__ int sm[ECAP];
    __shared__ int wTot[8];
    __shared__ int s_tot, s_base;
    int g = blockIdx.x;
    int tid = threadIdx.x, w = tid >> 5, lane = tid & 31;
    int n = g_eqN[g];
    if (n == 0) return;
    unsigned thr = g_thr[g];
    int rem = g_rem[g];
    float wv = unflip(thr);
    if (n <= ECAP) {
        int P = 1;
        while (P < n) P <<= 1;
        for (int i = tid; i < P; i += 256) sm[i] = (i < n) ? g_eqIdx[g * ECAP + i] : 0x7fffffff;
        __syncthreads();
        for (int kk = 2; kk <= P; kk <<= 1) {
            for (int jj = kk >> 1; jj > 0; jj >>= 1) {
                for (int i = tid; i < P; i += 256) {
                    int ix = i ^ jj;
                    if (ix > i) {
                        int a = sm[i], b = sm[ix];
                        bool up = ((i & kk) == 0);
                        if ((a > b) == up) { sm[i] = b; sm[ix] = a; }
                    }
                }
                __syncthreads();
            }
        }
        for (int i = tid; i < n; i += 256) {
            int t = sm[i];
            bool sel = i < rem;
            outMask[t] = sel ? 1.0f : 0.0f;
            if (sel) {
                outW[t] = wv;
                unsigned long long pk = g_pack[t];
                outNM[(int)(pk & 0xffffull)] = 1.0f;
                outNM[(int)((pk >> 16) & 0xffffull)] = 1.0f;
            } else {
                outW[t] = 0.0f;
            }
        }
    } else {
        // fallback: ordered scan of the full segment (never expected)
        int start = g_segStart[g];
        int cnt = g_segCnt[g];
        if (tid == 0) s_base = 0;
        __syncthreads();
        for (int i0 = 0; i0 < cnt; i0 += 256) {
            int i = i0 + tid;
            bool eq = false;
            if (i < cnt) eq = (g_ulog[start + i] == thr);
            unsigned bal = __ballot_sync(0xffffffffu, eq);
            int wpre = __popc(bal & ((1u << lane) - 1u));
            if (lane == 0) wTot[w] = __popc(bal);
            __syncthreads();
            if (tid == 0) {
                int acc = 0;
#pragma unroll
                for (int ww = 0; ww < 8; ww++) { int v = wTot[ww]; wTot[ww] = acc; acc += v; }
                s_tot = acc;
            }
            __syncthreads();
            if (eq) {
                int rank = s_base + wTot[w] + wpre;
                bool sel = rank < rem;
                int t = start + i;
                outMask[t] = sel ? 1.0f : 0.0f;
                if (sel) {
                    outW[t] = wv;
                    unsigned long long pk = g_pack[t];
                    outNM[(int)(pk & 0xffffull)] = 1.0f;
                    outNM[(int)((pk >> 16) & 0xffffull)] = 1.0f;
                } else {
                    outW[t] = 0.0f;
                }
            }
            __syncthreads();
            if (tid == 0) s_base += s_tot;
            __syncthreads();
        }
    }
}

// ---------------- launch ----------------
extern "C" void kernel_launch(void* const* d_in, const int* in_sizes, int n_in,
                              void* d_out, int out_size) {
    const float* h   = (const float*)d_in[0];
    const float* W1  = (const float*)d_in[1];
    const float* b1  = (const float*)d_in[2];
    const float* lng = (const float*)d_in[3];
    const float* lnb = (const float*)d_in[4];
    const float* W2  = (const float*)d_in[5];
    const float* b2  = (const float*)d_in[6];
    const int* pos   = (const int*)d_in[7];
    const int* neg   = (const int*)d_in[8];
    const int* nb    = (const int*)d_in[9];

    int N = in_sizes[9];
    int E = in_sizes[7] / 2;
    int T = 2 * E;
    int numChunks = (T + CH - 1) / CH;

    float* outMask = (float*)d_out;
    float* outW    = outMask + T;
    float* outNM   = outW + T;

    int zn = NSEG * 65536;
    if (N > zn) zn = N;
    int mlpGrid = NSM * WAVES;
    int MT = ((T + mlpGrid - 1) / mlpGrid + 31) & ~31;

    k_zero<<<(zn + 255) / 256, 256>>>(outNM, N);
    k_gemmP<<<296, 256>>>(h, W1, N);
    k_hist<<<numChunks, 256>>>(pos, neg, nb, E, T);
    k_scanC<<<NSEG, 256>>>(numChunks);
    k_scatter<<<numChunks, 256>>>(pos, neg, nb, E, T);
    k_mlp<<<mlpGrid, 256>>>(W1, b1, lng, lnb, W2, b2, T, MT);
    k_solve<<<NSEG, 256>>>();
    f_count<<<(T + 255) / 256, 256>>>(outMask, outW, outNM, T);
    f_mark<<<NSEG, 256>>>(outMask, outW, outNM);
    (void)n_in; (void)out_size;
}